// round 17
// baseline (speedup 1.0000x reference)
#include <cuda_runtime.h>
#include <cuda_fp16.h>
#include <cuda.h>
#include <cstdint>
#include <dlfcn.h>

#define CS 2048
#define CH 16
#define FA_C 0.10411754f   // 192^-0.5 * log2(e)

// ---------------- scratch (device globals, fp16 operands) -------------------
__device__ __align__(256) __half g_xh [(size_t)4096*2048];
__device__ __align__(256) __half g_wqah[(size_t)1536*2048];
__device__ __align__(256) __half g_wkvah[(size_t)576*2048];
__device__ __align__(256) __half g_wqbh[(size_t)3072*1536];
__device__ __align__(256) __half g_woh[(size_t)2048*2048];
__device__ __align__(256) __half g_wvh[(size_t)16*128*512];
__device__ __align__(256) __half g_wnh[(size_t)16*128*512];
__device__ __align__(256) __half g_q1 [(size_t)4096*1536];
__device__ __align__(256) __half g_kv [(size_t)4096*576];
__device__ __align__(256) __half g_q2 [(size_t)4096*3072];
__device__ __align__(256) __half g_kp [(size_t)4096*3072];
__device__ __align__(256) __half g_vt [(size_t)32*128*2048];
__device__ __align__(256) __half g_ov [(size_t)4096*2048];

// ---------------- ptx helpers ----------------
__device__ __forceinline__ void mma_fp16(float* c, const uint32_t* a, uint32_t b0, uint32_t b1) {
    asm volatile(
        "mma.sync.aligned.m16n8k16.row.col.f32.f16.f16.f32 "
        "{%0,%1,%2,%3},{%4,%5,%6,%7},{%8,%9},{%0,%1,%2,%3};"
        : "+f"(c[0]), "+f"(c[1]), "+f"(c[2]), "+f"(c[3])
        : "r"(a[0]), "r"(a[1]), "r"(a[2]), "r"(a[3]), "r"(b0), "r"(b1));
}
__device__ __forceinline__ void ldsm4(uint32_t* r, uint32_t addr) {
    asm volatile("ldmatrix.sync.aligned.m8n8.x4.shared.b16 {%0,%1,%2,%3}, [%4];"
        : "=r"(r[0]), "=r"(r[1]), "=r"(r[2]), "=r"(r[3]) : "r"(addr));
}
#define MBAR_INIT(a, c) \
    asm volatile("mbarrier.init.shared.b64 [%0], %1;" :: "r"(a), "r"(c) : "memory")
#define MBAR_EXPECT(a, tx) \
    asm volatile("mbarrier.arrive.expect_tx.shared.b64 _, [%0], %1;" :: "r"(a), "r"(tx) : "memory")
#define MBAR_WAIT(a, ph) do { \
    asm volatile("{\n\t.reg .pred P1;\n\tWL%=:\n\t" \
        "mbarrier.try_wait.parity.acquire.cta.shared::cta.b64 P1, [%0], %1, 0x989680;\n\t" \
        "@P1 bra.uni WD%=;\n\tbra.uni WL%=;\n\tWD%=:\n\t}" \
        :: "r"(a), "r"(ph) : "memory"); } while (0)
__device__ __forceinline__ void tma2d(uint32_t dst, const void* map, int x, int y, uint32_t mbar) {
    asm volatile(
        "cp.async.bulk.tensor.2d.shared::cta.global.tile.mbarrier::complete_tx::bytes "
        "[%0], [%1, {%2, %3}], [%4];"
        :: "r"(dst), "l"(map), "r"(x), "r"(y), "r"(mbar) : "memory");
}
__device__ __forceinline__ float ex2(float x) {
    float y; asm("ex2.approx.f32 %0, %1;" : "=f"(y) : "f"(x)); return y;
}

// ---------------- TMA fp16 GEMM (ldmatrix mainloop, unchanged) ----------------
#define NST 3
#define STAGE 32768
#define SMEM_TMA (1024 + NST * STAGE)

__global__ __launch_bounds__(256, 2) void gemm_h(
    const __grid_constant__ CUtensorMap mA,
    const __grid_constant__ CUtensorMap mB,
    int axh, int ayh, int axb, int ayb,
    int bxh, int byh, int bxb, int byb,
    float* __restrict__ Cf, __half* __restrict__ Chh,
    int ldc, long long strCh, long long strCb,
    int M, int N, int K, int causal, int kclamp)
{
    int bm = blockIdx.y, bn = blockIdx.x;
    if (kclamp) bm = gridDim.y - 1 - bm;
    if (causal && bn > bm) return;
    int zh = blockIdx.z & 15, zb = blockIdx.z >> 4;
    if (Cf) Cf += (long long)zh * strCh + (long long)zb * strCb;
    else    Chh += (long long)zh * strCh + (long long)zb * strCb;
    int m0 = bm * 128, n0 = bn * 128;
    int Keff = kclamp ? (K < m0 + 128 ? K : m0 + 128) : K;
    int ntk = Keff >> 6;

    extern __shared__ __align__(1024) char smem[];
    uint32_t sbase = (uint32_t)__cvta_generic_to_shared(smem);

    int tid = threadIdx.x;
    int wid = tid >> 5, lane = tid & 31;
    int wm = wid >> 1, wn = wid & 1;
    int g = lane >> 2, tg = lane & 3;

    uint32_t swzr  = (uint32_t)(lane & 7) << 4;
    uint32_t rowA  = (uint32_t)(((lane >> 3) & 1) * 8 + (lane & 7));
    uint32_t khA   = (uint32_t)(((lane >> 4) & 1) * 16);
    uint32_t rowB  = (uint32_t)(((lane >> 4) & 1) * 8 + (lane & 7));
    uint32_t khB   = (uint32_t)(((lane >> 3) & 1) * 16);

    if (tid == 0) {
#pragma unroll
        for (int s = 0; s < NST; s++) MBAR_INIT(sbase + s * 8, 1);
    }
    __syncthreads();

    int xa = zh * axh + zb * axb, ya = m0 + zh * ayh + zb * ayb;
    int xb = zh * bxh + zb * bxb, yb = n0 + zh * byh + zb * byb;

    auto issue = [&](int j, int jb) {
        uint32_t mb = sbase + jb * 8;
        uint32_t da = sbase + 1024 + jb * STAGE;
        int k0 = j * 64;
        MBAR_EXPECT(mb, STAGE);
        tma2d(da, &mA, xa + k0, ya, mb);
        tma2d(da + 16384, &mB, xb + k0, yb, mb);
    };

    if (tid == 0) {
        issue(0, 0);
        if (ntk > 1) issue(1, 1);
    }

    float acc[2][8][4];
#pragma unroll
    for (int mi = 0; mi < 2; mi++)
#pragma unroll
        for (int j = 0; j < 8; j++)
#pragma unroll
            for (int r = 0; r < 4; r++) acc[mi][j][r] = 0.f;

    int buf = 0, ph = 0;
    int pj = NST - 1, pbuf = NST - 1;

    for (int kt = 0; kt < ntk; kt++) {
        MBAR_WAIT(sbase + buf * 8, ph);
        uint32_t As_u = sbase + 1024 + buf * STAGE;
        uint32_t Bs_u = As_u + 16384;
#pragma unroll
        for (int ks = 0; ks < 4; ks++) {
            uint32_t cb = (uint32_t)(ks * 32);
            uint32_t a[2][4];
            ldsm4(a[0], As_u + (wm * 32 +      rowA) * 128 + ((cb + khA) ^ swzr));
            ldsm4(a[1], As_u + (wm * 32 + 16 + rowA) * 128 + ((cb + khA) ^ swzr));
#pragma unroll
            for (int p = 0; p < 4; p++) {
                uint32_t bb[4];
                ldsm4(bb, Bs_u + (wn * 64 + p * 16 + rowB) * 128 + ((cb + khB) ^ swzr));
                mma_fp16(acc[0][2*p],   a[0], bb[0], bb[1]);
                mma_fp16(acc[1][2*p],   a[1], bb[0], bb[1]);
                mma_fp16(acc[0][2*p+1], a[0], bb[2], bb[3]);
                mma_fp16(acc[1][2*p+1], a[1], bb[2], bb[3]);
            }
        }
        __syncthreads();
        if (tid == 0 && pj < ntk) issue(pj, pbuf);
        pj++;
        if (++pbuf == NST) pbuf = 0;
        if (++buf == NST) { buf = 0; ph ^= 1; }
    }

#pragma unroll
    for (int mi = 0; mi < 2; mi++) {
#pragma unroll
        for (int j = 0; j < 8; j++) {
            int row = m0 + wm * 32 + mi * 16 + g;
            int col = n0 + wn * 64 + j * 8 + 2 * tg;
            if (col < N) {
                float v0 = acc[mi][j][0], v1 = acc[mi][j][1];
                float v2 = acc[mi][j][2], v3 = acc[mi][j][3];
                if (Cf) {
                    *(float2*)&Cf[(long long)row * ldc + col] = make_float2(v0, v1);
                    *(float2*)&Cf[(long long)(row + 8) * ldc + col] = make_float2(v2, v3);
                } else {
                    *(__half2*)&Chh[(long long)row * ldc + col] = __floats2half2_rn(v0, v1);
                    *(__half2*)&Chh[(long long)(row + 8) * ldc + col] = __floats2half2_rn(v2, v3);
                }
            }
        }
    }
}

// ---------------- fused flash attention: 4x2 warp grid -----------------------
// All TMA tile bases MUST be 1024B-aligned (SW128 swizzle phase is absolute).
#define REDM_OFF 64
#define REDS_OFF 1088
#define SMQ_OFF 3072                      // 3*1024
#define RING_OFF (SMQ_OFF + 49152)        // 52224 = 51*1024
#define KVSTG 81920
#define SMEM_FA (RING_OFF + 2 * KVSTG)    // 216064

__global__ __launch_bounds__(256, 1) void flash_h(
    const __grid_constant__ CUtensorMap mQ,
    const __grid_constant__ CUtensorMap mK,
    const __grid_constant__ CUtensorMap mV,
    __half* __restrict__ ov, int bhoff)
{
    int qt = (int)gridDim.x - 1 - (int)blockIdx.x;   // heavy tiles first
    int bh = blockIdx.y + bhoff;
    int b = bh >> 4, h = bh & 15;
    int ntk = qt + 1;

    extern __shared__ __align__(1024) char smem[];
    uint32_t sbase = (uint32_t)__cvta_generic_to_shared(smem);
    float* redM = (float*)(smem + REDM_OFF);
    float* redS = (float*)(smem + REDS_OFF);

    int tid = threadIdx.x;
    int wid = tid >> 5, lane = tid & 31;
    int wm = wid >> 1, wn = wid & 1;
    int g = lane >> 2, tg = lane & 3;
    int rbase = wm * 32;

    uint32_t swzr = (uint32_t)(lane & 7) << 4;
    uint32_t rowA = (uint32_t)(((lane >> 3) & 1) * 8 + (lane & 7));
    uint32_t khA  = (uint32_t)(((lane >> 4) & 1) * 16);
    uint32_t rowB = (uint32_t)(((lane >> 4) & 1) * 8 + (lane & 7));
    uint32_t khB  = (uint32_t)(((lane >> 3) & 1) * 16);

    if (tid == 0) {
        MBAR_INIT(sbase + 0, 1);
        MBAR_INIT(sbase + 8, 1);
        MBAR_INIT(sbase + 16, 1);
    }
    __syncthreads();

    auto issueKV = [&](int kt, int st) {
        uint32_t mb = sbase + 8 + st * 8;
        uint32_t base = sbase + RING_OFF + st * KVSTG;
        MBAR_EXPECT(mb, KVSTG);
#pragma unroll
        for (int c = 0; c < 3; c++)
            tma2d(base + c * 16384, &mK, h * 192 + c * 64, b * 2048 + kt * 128, mb);
#pragma unroll
        for (int c = 0; c < 2; c++)
            tma2d(base + 49152 + c * 16384, &mV, kt * 128 + c * 64, bh * 128, mb);
    };

    if (tid == 0) {
        MBAR_EXPECT(sbase + 0, 49152);
#pragma unroll
        for (int c = 0; c < 3; c++)
            tma2d(sbase + SMQ_OFF + c * 16384, &mQ, h * 192 + c * 64, b * 2048 + qt * 128, sbase + 0);
        issueKV(0, 0);
        if (ntk > 1) issueKV(1, 1);
    }

    MBAR_WAIT(sbase + 0, 0);

    float of[2][16][4];
#pragma unroll
    for (int mi = 0; mi < 2; mi++)
#pragma unroll
        for (int j = 0; j < 16; j++)
#pragma unroll
            for (int r = 0; r < 4; r++) of[mi][j][r] = 0.f;
    float mr[2][2] = {{-1e30f, -1e30f}, {-1e30f, -1e30f}};
    float lr[2][2] = {{0.f, 0.f}, {0.f, 0.f}};

    for (int kt = 0; kt < ntk; kt++) {
        int st = kt & 1;
        MBAR_WAIT(sbase + 8 + st * 8, (kt >> 1) & 1);
        uint32_t kbs = sbase + RING_OFF + st * KVSTG;
        uint32_t vbs = kbs + 49152;

        // ---- S = Q @ K^T  (warp: 32 rows x 64 keys) ----
        float sj[2][8][4];
#pragma unroll
        for (int mi = 0; mi < 2; mi++)
#pragma unroll
            for (int j = 0; j < 8; j++)
#pragma unroll
                for (int r = 0; r < 4; r++) sj[mi][j][r] = 0.f;
#pragma unroll
        for (int kk = 0; kk < 12; kk++) {
            uint32_t qch = sbase + SMQ_OFF + (kk >> 2) * 16384;
            uint32_t kch = kbs + (kk >> 2) * 16384;
            uint32_t cb = (uint32_t)((kk & 3) * 32);
            uint32_t a[2][4];
            ldsm4(a[0], qch + (rbase +      rowA) * 128 + ((cb + khA) ^ swzr));
            ldsm4(a[1], qch + (rbase + 16 + rowA) * 128 + ((cb + khA) ^ swzr));
#pragma unroll
            for (int p = 0; p < 4; p++) {
                uint32_t bb[4];
                ldsm4(bb, kch + (wn * 64 + p * 16 + rowB) * 128 + ((cb + khB) ^ swzr));
                mma_fp16(sj[0][2*p],   a[0], bb[0], bb[1]);
                mma_fp16(sj[0][2*p+1], a[0], bb[2], bb[3]);
                mma_fp16(sj[1][2*p],   a[1], bb[0], bb[1]);
                mma_fp16(sj[1][2*p+1], a[1], bb[2], bb[3]);
            }
        }

        // ---- causal mask on diagonal tile ----
        if (kt == qt) {
#pragma unroll
            for (int mi = 0; mi < 2; mi++) {
                int r0 = rbase + mi * 16 + g, r1 = r0 + 8;
#pragma unroll
                for (int jn = 0; jn < 8; jn++) {
                    int c0 = wn * 64 + jn * 8 + 2 * tg, c1 = c0 + 1;
                    if (c0 > r0) sj[mi][jn][0] = -1e30f;
                    if (c1 > r0) sj[mi][jn][1] = -1e30f;
                    if (c0 > r1) sj[mi][jn][2] = -1e30f;
                    if (c1 > r1) sj[mi][jn][3] = -1e30f;
                }
            }
        }

        // ---- local row max, quad reduce, cross-warp exchange ----
        float mx[2][2] = {{-1e30f, -1e30f}, {-1e30f, -1e30f}};
#pragma unroll
        for (int mi = 0; mi < 2; mi++)
#pragma unroll
            for (int jn = 0; jn < 8; jn++) {
                mx[mi][0] = fmaxf(mx[mi][0], fmaxf(sj[mi][jn][0], sj[mi][jn][1]));
                mx[mi][1] = fmaxf(mx[mi][1], fmaxf(sj[mi][jn][2], sj[mi][jn][3]));
            }
#pragma unroll
        for (int mi = 0; mi < 2; mi++)
#pragma unroll
            for (int hh = 0; hh < 2; hh++) {
                mx[mi][hh] = fmaxf(mx[mi][hh], __shfl_xor_sync(0xffffffffu, mx[mi][hh], 1));
                mx[mi][hh] = fmaxf(mx[mi][hh], __shfl_xor_sync(0xffffffffu, mx[mi][hh], 2));
            }
        if (tg == 0) {
            redM[wn * 128 + rbase +      g] = mx[0][0];
            redM[wn * 128 + rbase +  8 + g] = mx[0][1];
            redM[wn * 128 + rbase + 16 + g] = mx[1][0];
            redM[wn * 128 + rbase + 24 + g] = mx[1][1];
        }
        __syncthreads();

        float f[2][2], mn[2][2];
#pragma unroll
        for (int mi = 0; mi < 2; mi++)
#pragma unroll
            for (int hh = 0; hh < 2; hh++) {
                float mo = redM[(1 - wn) * 128 + rbase + mi * 16 + hh * 8 + g];
                float m2 = fmaxf(mx[mi][hh], mo);
                mn[mi][hh] = fmaxf(mr[mi][hh], m2);
                f[mi][hh] = ex2((mr[mi][hh] - mn[mi][hh]) * FA_C);
                mr[mi][hh] = mn[mi][hh];
            }

        // ---- exp, pack to A-frags, partial sums ----
        float sm[2][2] = {{0.f, 0.f}, {0.f, 0.f}};
        uint32_t pjf[2][4][4];
#pragma unroll
        for (int mi = 0; mi < 2; mi++)
#pragma unroll
            for (int u = 0; u < 4; u++) {
                float e00 = ex2((sj[mi][2*u][0] - mn[mi][0]) * FA_C);
                float e01 = ex2((sj[mi][2*u][1] - mn[mi][0]) * FA_C);
                float e02 = ex2((sj[mi][2*u][2] - mn[mi][1]) * FA_C);
                float e03 = ex2((sj[mi][2*u][3] - mn[mi][1]) * FA_C);
                float e10 = ex2((sj[mi][2*u+1][0] - mn[mi][0]) * FA_C);
                float e11 = ex2((sj[mi][2*u+1][1] - mn[mi][0]) * FA_C);
                float e12 = ex2((sj[mi][2*u+1][2] - mn[mi][1]) * FA_C);
                float e13 = ex2((sj[mi][2*u+1][3] - mn[mi][1]) * FA_C);
                sm[mi][0] += e00 + e01 + e10 + e11;
                sm[mi][1] += e02 + e03 + e12 + e13;
                __half2 h0 = __floats2half2_rn(e00, e01);
                __half2 h1 = __floats2half2_rn(e02, e03);
                __half2 h2 = __floats2half2_rn(e10, e11);
                __half2 h3 = __floats2half2_rn(e12, e13);
                pjf[mi][u][0] = *(uint32_t*)&h0;
                pjf[mi][u][1] = *(uint32_t*)&h1;
                pjf[mi][u][2] = *(uint32_t*)&h2;
                pjf[mi][u][3] = *(uint32_t*)&h3;
            }
#pragma unroll
        for (int mi = 0; mi < 2; mi++)
#pragma unroll
            for (int hh = 0; hh < 2; hh++) {
                sm[mi][hh] += __shfl_xor_sync(0xffffffffu, sm[mi][hh], 1);
                sm[mi][hh] += __shfl_xor_sync(0xffffffffu, sm[mi][hh], 2);
            }
        if (tg == 0) {
            redS[wn * 128 + rbase +      g] = sm[0][0];
            redS[wn * 128 + rbase +  8 + g] = sm[0][1];
            redS[wn * 128 + rbase + 16 + g] = sm[1][0];
            redS[wn * 128 + rbase + 24 + g] = sm[1][1];
        }
        __syncthreads();
#pragma unroll
        for (int mi = 0; mi < 2; mi++)
#pragma unroll
            for (int hh = 0; hh < 2; hh++) {
                float so = redS[(1 - wn) * 128 + rbase + mi * 16 + hh * 8 + g];
                lr[mi][hh] = lr[mi][hh] * f[mi][hh] + sm[mi][hh] + so;
            }

        // ---- rescale O ----
#pragma unroll
        for (int mi = 0; mi < 2; mi++)
#pragma unroll
            for (int j = 0; j < 16; j++) {
                of[mi][j][0] *= f[mi][0]; of[mi][j][1] *= f[mi][0];
                of[mi][j][2] *= f[mi][1]; of[mi][j][3] *= f[mi][1];
            }

        // ---- O += P @ V  (warp's 64-key half; V chunk = wn) ----
        uint32_t vch = vbs + (uint32_t)wn * 16384;
#pragma unroll
        for (int u = 0; u < 4; u++) {
            uint32_t cb = (uint32_t)(u * 32);
#pragma unroll
            for (int p = 0; p < 8; p++) {
                uint32_t bb[4];
                ldsm4(bb, vch + (p * 16 + rowB) * 128 + ((cb + khB) ^ swzr));
                mma_fp16(of[0][2*p],   pjf[0][u], bb[0], bb[1]);
                mma_fp16(of[0][2*p+1], pjf[0][u], bb[2], bb[3]);
                mma_fp16(of[1][2*p],   pjf[1][u], bb[0], bb[1]);
                mma_fp16(of[1][2*p+1], pjf[1][u], bb[2], bb[3]);
            }
        }

        __syncthreads();
        if (tid == 0 && kt + 2 < ntk) issueKV(kt + 2, st);
    }

    // ---- combine O across wn pairs (ring smem is dead now) ----
    float* cbuf = (float*)(smem + RING_OFF);
    if (wn == 1) {
#pragma unroll
        for (int mi = 0; mi < 2; mi++)
#pragma unroll
            for (int jn = 0; jn < 16; jn++) {
                int r0 = rbase + mi * 16 + g;
                int c = jn * 8 + 2 * tg;
                cbuf[r0 * 128 + c]           = of[mi][jn][0];
                cbuf[r0 * 128 + c + 1]       = of[mi][jn][1];
                cbuf[(r0 + 8) * 128 + c]     = of[mi][jn][2];
                cbuf[(r0 + 8) * 128 + c + 1] = of[mi][jn][3];
            }
    }
    __syncthreads();
    if (wn == 0) {
        float inv[2][2];
#pragma unroll
        for (int mi = 0; mi < 2; mi++) {
            inv[mi][0] = 1.f / lr[mi][0];
            inv[mi][1] = 1.f / lr[mi][1];
        }
        long long rowg = (long long)b * 2048 + qt * 128;
#pragma unroll
        for (int mi = 0; mi < 2; mi++)
#pragma unroll
            for (int jn = 0; jn < 16; jn++) {
                int r0 = rbase + mi * 16 + g;
                int c = jn * 8 + 2 * tg;
                float v0 = (of[mi][jn][0] + cbuf[r0 * 128 + c])           * inv[mi][0];
                float v1 = (of[mi][jn][1] + cbuf[r0 * 128 + c + 1])       * inv[mi][0];
                float v2 = (of[mi][jn][2] + cbuf[(r0 + 8) * 128 + c])     * inv[mi][1];
                float v3 = (of[mi][jn][3] + cbuf[(r0 + 8) * 128 + c + 1]) * inv[mi][1];
                int d = h * 128 + c;
                *(__half2*)&ov[(rowg + r0) * 2048 + d]     = __floats2half2_rn(v0, v1);
                *(__half2*)&ov[(rowg + r0 + 8) * 2048 + d] = __floats2half2_rn(v2, v3);
            }
    }
}

// ---------------- prep: fp32 -> fp16 copies ----------------------------------
__global__ void f2h_copy(const float* __restrict__ s, __half* __restrict__ d, long long n4)
{
    long long i = (long long)blockIdx.x * 256 + threadIdx.x;
    if (i >= n4) return;
    float4 v = ((const float4*)s)[i];
    __half2 h0 = __floats2half2_rn(v.x, v.y);
    __half2 h1 = __floats2half2_rn(v.z, v.w);
    ((uint2*)d)[i] = make_uint2(*(uint32_t*)&h0, *(uint32_t*)&h1);
}

__global__ void f2h_head(const float* __restrict__ wkvb, __half* __restrict__ d, int srcOff)
{
    long long i4 = (long long)blockIdx.x * 256 + threadIdx.x;
    long long head = i4 >> 14, off = (i4 & 16383) * 4;
    float4 v = *(const float4*)(wkvb + head * 131072 + srcOff + off);
    __half2 h0 = __floats2half2_rn(v.x, v.y);
    __half2 h1 = __floats2half2_rn(v.z, v.w);
    ((uint2*)d)[i4] = make_uint2(*(uint32_t*)&h0, *(uint32_t*)&h1);
}

// ---------------- rmsnorm rows (fp16 data, fp32 math) ------------------------
__global__ void rmsnorm_h(__half* __restrict__ x, const float* __restrict__ w, int n)
{
    long long row = blockIdx.x;
    __half* r = x + row * n;
    float ss = 0.f;
    for (int i = threadIdx.x; i < n; i += 256) { float v = __half2float(r[i]); ss += v * v; }
    __shared__ float red[8];
#pragma unroll
    for (int o = 16; o; o >>= 1) ss += __shfl_xor_sync(0xffffffffu, ss, o);
    if ((threadIdx.x & 31) == 0) red[threadIdx.x >> 5] = ss;
    __syncthreads();
    float tot = 0.f;
#pragma unroll
    for (int wv = 0; wv < 8; wv++) tot += red[wv];
    float scale = rsqrtf(tot / (float)n + 1e-6f);
    for (int i = threadIdx.x; i < n; i += 256)
        r[i] = __float2half_rn(__half2float(r[i]) * scale * w[i]);
}

// -------- kv row: rmsnorm first 512 (+w), rope last 64 (fp16 data) -----------
__global__ void kv_process_h(__half* __restrict__ kv, const float* __restrict__ w,
                             const float* __restrict__ cosp, const float* __restrict__ sinp)
{
    int row = blockIdx.x;
    int s = row % CS;
    __half* r = kv + (long long)row * 576;
    float ss = 0.f;
    for (int i = threadIdx.x; i < 512; i += 128) { float v = __half2float(r[i]); ss += v * v; }
    __shared__ float red[4];
#pragma unroll
    for (int o = 16; o; o >>= 1) ss += __shfl_xor_sync(0xffffffffu, ss, o);
    if ((threadIdx.x & 31) == 0) red[threadIdx.x >> 5] = ss;
    __syncthreads();
    float tot = red[0] + red[1] + red[2] + red[3];
    float scale = rsqrtf(tot / 512.f + 1e-6f);
    for (int i = threadIdx.x; i < 512; i += 128)
        r[i] = __float2half_rn(__half2float(r[i]) * scale * w[i]);
    if (threadIdx.x < 32) {
        int i = threadIdx.x;
        float x0 = __half2float(r[512 + 2 * i]), x1 = __half2float(r[513 + 2 * i]);
        float c = cosp[s * 32 + i], sn = sinp[s * 32 + i];
        r[512 + 2 * i] = __float2half_rn(x0 * c - x1 * sn);
        r[513 + 2 * i] = __float2half_rn(x0 * sn + x1 * c);
    }
}

// ---------------- RoPE on q2 rows (per-batch half) ----------------------------
__global__ void rope_q2(__half* __restrict__ q2,
                        const float* __restrict__ cosp, const float* __restrict__ sinp)
{
    int idx = blockIdx.x * 256 + threadIdx.x;
    if (idx >= 2048 * CH * 32) return;
    int i = idx & 31;
    int h = (idx >> 5) & 15;
    int row = idx >> 9;
    int s = row;
    __half* p = q2 + (long long)row * 3072 + h * 192 + 128 + 2 * i;
    float x0 = __half2float(p[0]), x1 = __half2float(p[1]);
    float c = cosp[s * 32 + i], sn = sinp[s * 32 + i];
    p[0] = __float2half_rn(x0 * c - x1 * sn);
    p[1] = __float2half_rn(x0 * sn + x1 * c);
}

// ---------------- duplicate roped k_pe into Kp per head -----------------------
__global__ void kpe_dup(const __half* __restrict__ kv, __half* __restrict__ kp)
{
    int idx = blockIdx.x * 256 + threadIdx.x;
    if (idx >= 2 * 2048 * 16 * 32) return;
    int j2 = idx & 31;
    int h = (idx >> 5) & 15;
    int row = idx >> 9;
    uint32_t v = *(const uint32_t*)(kv + (long long)row * 576 + 512 + 2 * j2);
    *(uint32_t*)(kp + (long long)row * 3072 + h * 192 + 128 + 2 * j2) = v;
}

// ---------------- host: tensormap encode via dlopen(libcuda) -----------------
typedef CUresult (*PFN_tmEncode)(
    CUtensorMap*, CUtensorMapDataType, cuuint32_t, void*,
    const cuuint64_t*, const cuuint64_t*, const cuuint32_t*, const cuuint32_t*,
    CUtensorMapInterleave, CUtensorMapSwizzle, CUtensorMapL2promotion,
    CUtensorMapFloatOOBfill);

static PFN_tmEncode tm_encode()
{
    static PFN_tmEncode fn = nullptr;
    if (!fn) {
        void* h = dlopen("libcuda.so.1", RTLD_NOW | RTLD_GLOBAL);
        if (!h) h = dlopen("libcuda.so", RTLD_NOW | RTLD_GLOBAL);
        if (h) fn = (PFN_tmEncode)dlsym(h, "cuTensorMapEncodeTiled");
    }
    return fn;
}

static void make_map_h(CUtensorMap* m, void* base, long long cols, long long rows, long long ld)
{
    cuuint64_t dims[2]    = {(cuuint64_t)cols, (cuuint64_t)rows};
    cuuint64_t strides[1] = {(cuuint64_t)(ld * 2)};
    cuuint32_t box[2]     = {64u, 128u};
    cuuint32_t es[2]      = {1u, 1u};
    tm_encode()(m, CU_TENSOR_MAP_DATA_TYPE_FLOAT16, 2, base, dims, strides, box, es,
                CU_TENSOR_MAP_INTERLEAVE_NONE, CU_TENSOR_MAP_SWIZZLE_128B,
                CU_TENSOR_MAP_L2_PROMOTION_L2_128B, CU_TENSOR_MAP_FLOAT_OOB_FILL_NONE);
}

// ---------------------------------------------------------------------------
extern "C" void kernel_launch(void* const* d_in, const int* in_sizes, int n_in,
                              void* d_out, int out_size)
{
    (void)in_sizes; (void)n_in; (void)out_size;
    const float* x        = (const float*)d_in[0];
    const float* wq_a     = (const float*)d_in[1];
    const float* q_norm_w = (const float*)d_in[2];
    const float* wq_b     = (const float*)d_in[3];
    const float* wkv_a    = (const float*)d_in[4];
    const float* kv_norm_w= (const float*)d_in[5];
    const float* wkv_b    = (const float*)d_in[6];
    const float* wo       = (const float*)d_in[7];
    const float* cosp     = (const float*)d_in[8];
    const float* sinp     = (const float*)d_in[9];
    float* out = (float*)d_out;

    __half *xh, *wqah, *wkvah, *wqbh, *woh, *wvh, *wnh;
    __half *q1, *kvb, *q2, *kp, *vt, *ov;
    cudaGetSymbolAddress((void**)&xh,   g_xh);
    cudaGetSymbolAddress((void**)&wqah, g_wqah);
    cudaGetSymbolAddress((void**)&wkvah,g_wkvah);
    cudaGetSymbolAddress((void**)&wqbh, g_wqbh);
    cudaGetSymbolAddress((void**)&woh,  g_woh);
    cudaGetSymbolAddress((void**)&wvh,  g_wvh);
    cudaGetSymbolAddress((void**)&wnh,  g_wnh);
    cudaGetSymbolAddress((void**)&q1,   g_q1);
    cudaGetSymbolAddress((void**)&kvb,  g_kv);
    cudaGetSymbolAddress((void**)&q2,   g_q2);
    cudaGetSymbolAddress((void**)&kp,   g_kp);
    cudaGetSymbolAddress((void**)&vt,   g_vt);
    cudaGetSymbolAddress((void**)&ov,   g_ov);

    cudaFuncSetAttribute(gemm_h, cudaFuncAttributeMaxDynamicSharedMemorySize, SMEM_TMA);
    cudaFuncSetAttribute(flash_h, cudaFuncAttributeMaxDynamicSharedMemorySize, SMEM_FA);

    CUtensorMap mXH0, mXH1, mWQA, mWKVA, mWQB, mWO, mWNH, mWVH;
    CUtensorMap mXHf, mQ1a, mQ1b, mKV, mQ2, mKP, mVT, mOVa, mOVb;
    make_map_h(&mXHf, xh, 2048, 4096, 2048);
    make_map_h(&mXH0, xh, 2048, 2048, 2048);
    make_map_h(&mXH1, xh + (size_t)2048*2048, 2048, 2048, 2048);
    make_map_h(&mWQA, wqah, 2048, 1536, 2048);
    make_map_h(&mWKVA,wkvah,2048, 576,  2048);
    make_map_h(&mWQB, wqbh, 1536, 3072, 1536);
    make_map_h(&mWO,  woh,  2048, 2048, 2048);
    make_map_h(&mWNH, wnh,  512,  2048, 512);
    make_map_h(&mWVH, wvh,  512,  2048, 512);
    make_map_h(&mQ1a, q1, 1536, 2048, 1536);
    make_map_h(&mQ1b, q1 + (size_t)2048*1536, 1536, 2048, 1536);
    make_map_h(&mKV,  kvb,  576,  4096, 576);
    make_map_h(&mQ2,  q2,   3072, 4096, 3072);
    make_map_h(&mKP,  kp,   3072, 4096, 3072);
    make_map_h(&mVT,  vt,   2048, 4096, 2048);
    make_map_h(&mOVa, ov, 2048, 2048, 2048);
    make_map_h(&mOVb, ov + (size_t)2048*2048, 2048, 2048, 2048);

    // ---- streams/events: created ONCE; origin + 3 side streams only
    static bool s_init = false;
    static cudaStream_t s1, s2, s3;
    static cudaEvent_t evRoot, evX, evWQA, evWQB, evWO, evWNH, evKVP, evKP, evVT, evB;
    if (!s_init) {
        cudaStreamCreateWithFlags(&s1, cudaStreamNonBlocking);
        cudaStreamCreateWithFlags(&s2, cudaStreamNonBlocking);
        cudaStreamCreateWithFlags(&s3, cudaStreamNonBlocking);
        cudaEventCreateWithFlags(&evRoot, cudaEventDisableTiming);
        cudaEventCreateWithFlags(&evX,    cudaEventDisableTiming);
        cudaEventCreateWithFlags(&evWQA,  cudaEventDisableTiming);
        cudaEventCreateWithFlags(&evWQB,  cudaEventDisableTiming);
        cudaEventCreateWithFlags(&evWO,   cudaEventDisableTiming);
        cudaEventCreateWithFlags(&evWNH,  cudaEventDisableTiming);
        cudaEventCreateWithFlags(&evKVP,  cudaEventDisableTiming);
        cudaEventCreateWithFlags(&evKP,   cudaEventDisableTiming);
        cudaEventCreateWithFlags(&evVT,   cudaEventDisableTiming);
        cudaEventCreateWithFlags(&evB,    cudaEventDisableTiming);
        s_init = true;
    }

    // ---- origin: full x convert, wqa convert, then b0 Q chain
    cudaEventRecord(evRoot, 0);
    f2h_copy<<<8192, 256>>>(x, xh, 2097152);
    cudaEventRecord(evX, 0);
    f2h_copy<<<3072, 256>>>(wq_a, wqah, 786432);
    cudaEventRecord(evWQA, 0);

    // ---- s1: big weight converts, then b1 Q chain
    cudaStreamWaitEvent(s1, evRoot, 0);
    f2h_copy<<<4608, 256, 0, s1>>>(wq_b, wqbh, 1179648);
    cudaEventRecord(evWQB, s1);
    f2h_copy<<<4096, 256, 0, s1>>>(wo, woh, 1048576);
    cudaEventRecord(evWO, s1);

    // ---- s3: per-head weight converts, later V_h
    cudaStreamWaitEvent(s3, evRoot, 0);
    f2h_head<<<1024, 256, 0, s3>>>(wkv_b, wnh, 0);
    cudaEventRecord(evWNH, s3);
    f2h_head<<<1024, 256, 0, s3>>>(wkv_b, wvh, 65536);

    // ---- s2: KV chain (both batches)
    cudaStreamWaitEvent(s2, evX, 0);
    f2h_copy<<<1152, 256, 0, s2>>>(wkv_a, wkvah, 294912);
    gemm_h<<<dim3(5, 32, 1), 256, SMEM_TMA, s2>>>(mXHf, mWKVA, 0,0,0,0, 0,0,0,0,
        nullptr, kvb, 576, 0, 0, 4096, 576, 2048, 0, 0);
    kv_process_h<<<4096, 128, 0, s2>>>(kvb, kv_norm_w, cosp, sinp);
    cudaEventRecord(evKVP, s2);
    cudaStreamWaitEvent(s2, evWNH, 0);
    gemm_h<<<dim3(1, 16, 32), 256, SMEM_TMA, s2>>>(mKV, mWNH, 0,0,0,2048, 0,128,0,0,
        nullptr, kp, 3072, 192, (long long)2048*3072, 2048, 128, 512, 0, 0);
    kpe_dup<<<8192, 256, 0, s2>>>(kvb, kp);
    cudaEventRecord(evKP, s2);

    // ---- s3 continued: V_h (both batches)
    cudaStreamWaitEvent(s3, evKVP, 0);
    gemm_h<<<dim3(16, 1, 32), 256, SMEM_TMA, s3>>>(mWVH, mKV, 0,128,0,0, 0,0,0,2048,
        nullptr, vt, 2048, (long long)128*2048, (long long)16*128*2048,
        128, 2048, 512, 0, 0);
    cudaEventRecord(evVT, s3);

    // ---- origin: b0 Q chain
    gemm_h<<<dim3(12, 16, 1), 256, SMEM_TMA>>>(mXH0, mWQA, 0,0,0,0, 0,0,0,0,
        nullptr, q1, 1536, 0, 0, 2048, 1536, 2048, 0, 0);
    rmsnorm_h<<<2048, 256>>>(q1, q_norm_w, 1536);
    cudaStreamWaitEvent(0, evWQB, 0);
    gemm_h<<<dim3(24, 16, 1), 256, SMEM_TMA>>>(mQ1a, mWQB, 0,0,0,0, 0,0,0,0,
        nullptr, q2, 3072, 0, 0, 2048, 3072, 1536, 0, 0);
    rope_q2<<<4096, 256>>>(q2, cosp, sinp);
    cudaStreamWaitEvent(0, evKP, 0);
    cudaStreamWaitEvent(0, evVT, 0);
    flash_h<<<dim3(16, 16, 1), 256, SMEM_FA>>>(mQ2, mKP, mVT, ov, 0);
    cudaStreamWaitEvent(0, evWO, 0);
    gemm_h<<<dim3(16, 16, 1), 256, SMEM_TMA>>>(mOVa, mWO, 0,0,0,0, 0,0,0,0,
        out, nullptr, 2048, 0, 0, 2048, 2048, 2048, 0, 0);

    // ---- s1 continued: b1 Q chain
    cudaStreamWaitEvent(s1, evX, 0);
    cudaStreamWaitEvent(s1, evWQA, 0);
    gemm_h<<<dim3(12, 16, 1), 256, SMEM_TMA, s1>>>(mXH1, mWQA, 0,0,0,0, 0,0,0,0,
        nullptr, q1 + (size_t)2048*1536, 1536, 0, 0, 2048, 1536, 2048, 0, 0);
    rmsnorm_h<<<2048, 256, 0, s1>>>(q1 + (size_t)2048*1536, q_norm_w, 1536);
    gemm_h<<<dim3(24, 16, 1), 256, SMEM_TMA, s1>>>(mQ1b, mWQB, 0,0,0,0, 0,0,0,0,
        nullptr, q2 + (size_t)2048*3072, 3072, 0, 0, 2048, 3072, 1536, 0, 0);
    rope_q2<<<4096, 256, 0, s1>>>(q2 + (size_t)2048*3072, cosp, sinp);
    cudaStreamWaitEvent(s1, evKP, 0);
    cudaStreamWaitEvent(s1, evVT, 0);
    flash_h<<<dim3(16, 16, 1), 256, SMEM_FA, s1>>>(mQ2, mKP, mVT, ov, 16);
    gemm_h<<<dim3(16, 16, 1), 256, SMEM_TMA, s1>>>(mOVb, mWO, 0,0,0,0, 0,0,0,0,
        out + (size_t)2048*2048, nullptr, 2048, 0, 0, 2048, 2048, 2048, 0, 0);
    cudaEventRecord(evB, s1);

    // ---- join s1 back into origin
    cudaStreamWaitEvent(0, evB, 0);
}